// round 1
// baseline (speedup 1.0000x reference)
#include <cuda_runtime.h>
#include <math.h>

#define NN 20000
#define EE 320000
#define EH 160000
#define EPSV 1e-6f

// ---------------- scratch (static device globals; no allocs) ----------------
__device__ float g_h1[NN * 64];        // hidden of input MLP / hidden of output MLP
__device__ float g_h[NN * 128];        // h, then h3 updated in place
__device__ float g_P[NN * 128];        // [A | B] per node
__device__ float g_Wab[128 * 128];     // packed w_map1 for A|B gemm
__device__ float g_maps[EE * 4];       // edge restriction maps (2x2)
__device__ float g_Dinv[NN * 4];       // D^{-1/2} blocks (2x2 symmetric)
__device__ float g_diagn[NN * 4];      // normalized diag blocks
__device__ float g_offn[EE * 4];       // normalized off-diag blocks
__device__ float g_xw2[NN * 128];      // h3 @ W2^T
__device__ float g_Ht[NN * 128];       // W1^T applied
__device__ int g_deg[NN];
__device__ int g_cursor[NN];
__device__ int g_rowptr[NN + 1];
__device__ int g_adj[EE];

__device__ __forceinline__ float eluf(float v) {
    return v > 0.f ? v : (expf(v) - 1.f);
}

// ---------------- generic tiled fp32 GEMM: C = act(A[M,K] @ W[N,K]^T + bias) ----------------
template <bool RELU>
__global__ void __launch_bounds__(256) gemm_tn(const float* __restrict__ A,
                                               const float* __restrict__ W,
                                               const float* __restrict__ bias,
                                               float* __restrict__ C,
                                               int M, int N, int K) {
    __shared__ float As[16][68];
    __shared__ float Bs[16][68];
    int tid = threadIdx.x;
    int tx = tid & 15, ty = tid >> 4;
    int bm = blockIdx.y * 64, bn = blockIdx.x * 64;

    float acc[4][4] = {};

    int lr = tid >> 2;         // 0..63  (row within tile)
    int lk = (tid & 3) * 4;    // k-quad within 16

    const float* Aptr = A + (size_t)(bm + lr) * K + lk;
    const float* Wptr = W + (size_t)(bn + lr) * K + lk;
    bool avalid = (bm + lr) < M;
    bool wvalid = (bn + lr) < N;

    for (int k0 = 0; k0 < K; k0 += 16) {
        float4 av = avalid ? *(const float4*)(Aptr + k0) : make_float4(0.f, 0.f, 0.f, 0.f);
        float4 wv = wvalid ? *(const float4*)(Wptr + k0) : make_float4(0.f, 0.f, 0.f, 0.f);
        As[lk + 0][lr] = av.x; As[lk + 1][lr] = av.y;
        As[lk + 2][lr] = av.z; As[lk + 3][lr] = av.w;
        Bs[lk + 0][lr] = wv.x; Bs[lk + 1][lr] = wv.y;
        Bs[lk + 2][lr] = wv.z; Bs[lk + 3][lr] = wv.w;
        __syncthreads();
#pragma unroll
        for (int kk = 0; kk < 16; kk++) {
            float4 a = *(const float4*)(&As[kk][ty * 4]);
            float4 b = *(const float4*)(&Bs[kk][tx * 4]);
            float ar[4] = {a.x, a.y, a.z, a.w};
            float br[4] = {b.x, b.y, b.z, b.w};
#pragma unroll
            for (int i = 0; i < 4; i++)
#pragma unroll
                for (int j = 0; j < 4; j++) acc[i][j] += ar[i] * br[j];
        }
        __syncthreads();
    }

#pragma unroll
    for (int i = 0; i < 4; i++) {
        int m = bm + ty * 4 + i;
        if (m < M) {
#pragma unroll
            for (int j = 0; j < 4; j++) {
                int nn = bn + tx * 4 + j;
                if (nn < N) {
                    float v = acc[i][j] + (bias ? bias[nn] : 0.f);
                    if (RELU) v = fmaxf(v, 0.f);
                    C[(size_t)m * N + nn] = v;
                }
            }
        }
    }
}

// ---------------- prep: pack Wab, zero counters ----------------
__global__ void prep_k(const float* __restrict__ w_map1) {
    int i = blockIdx.x * blockDim.x + threadIdx.x;
    if (i < 128 * 128) {
        int j = i >> 7, k = i & 127;
        g_Wab[i] = (j < 64) ? w_map1[j * 256 + k] : w_map1[(j - 64) * 256 + 128 + k];
    }
    if (i < NN) {
        g_deg[i] = 0;
        g_cursor[i] = 0;
    }
}

// ---------------- CSR build ----------------
__global__ void hist_k(const int* __restrict__ src) {
    int e = blockIdx.x * blockDim.x + threadIdx.x;
    if (e < EE) atomicAdd(&g_deg[src[e]], 1);
}

__global__ void __launch_bounds__(1024) scan_k() {
    __shared__ int wsum[32];
    __shared__ int carry;
    int t = threadIdx.x, l = t & 31, w = t >> 5;
    if (t == 0) { carry = 0; g_rowptr[0] = 0; }
    __syncthreads();
    for (int base = 0; base < NN; base += 1024) {
        int v = (base + t < NN) ? g_deg[base + t] : 0;
        int x = v;
#pragma unroll
        for (int o = 1; o < 32; o <<= 1) {
            int y = __shfl_up_sync(0xFFFFFFFFu, x, o);
            if (l >= o) x += y;
        }
        if (l == 31) wsum[w] = x;
        __syncthreads();
        if (w == 0) {
            int y = wsum[l];
#pragma unroll
            for (int o = 1; o < 32; o <<= 1) {
                int z = __shfl_up_sync(0xFFFFFFFFu, y, o);
                if (l >= o) y += z;
            }
            wsum[l] = y;
        }
        __syncthreads();
        int off = carry + (w > 0 ? wsum[w - 1] : 0);
        if (base + t < NN) g_rowptr[base + t + 1] = off + x;
        __syncthreads();
        if (t == 0) carry += wsum[31];
        __syncthreads();
    }
}

__global__ void scatter_k(const int* __restrict__ src) {
    int e = blockIdx.x * blockDim.x + threadIdx.x;
    if (e < EE) {
        int s = src[e];
        int p = atomicAdd(&g_cursor[s], 1);
        g_adj[g_rowptr[s] + p] = e;
    }
}

// ---------------- edge restriction maps (warp per edge) ----------------
__global__ void __launch_bounds__(256) edge_maps_k(const int* __restrict__ src,
                                                   const int* __restrict__ dst,
                                                   const float* __restrict__ b_map1,
                                                   const float* __restrict__ w_map2,
                                                   const float* __restrict__ b_map2) {
    int w = threadIdx.x >> 5, l = threadIdx.x & 31;
    int e = blockIdx.x * 8 + w;
    if (e >= EE) return;
    int s = src[e], d = dst[e];
    float h0 = g_P[s * 128 + l] + g_P[d * 128 + 64 + l] + b_map1[l];
    float h1 = g_P[s * 128 + 32 + l] + g_P[d * 128 + 96 + l] + b_map1[32 + l];
    h0 = fmaxf(h0, 0.f);
    h1 = fmaxf(h1, 0.f);
    float p0 = h0 * w_map2[l] + h1 * w_map2[32 + l];
    float p1 = h0 * w_map2[64 + l] + h1 * w_map2[96 + l];
    float p2 = h0 * w_map2[128 + l] + h1 * w_map2[160 + l];
    float p3 = h0 * w_map2[192 + l] + h1 * w_map2[224 + l];
#pragma unroll
    for (int o = 16; o > 0; o >>= 1) {
        p0 += __shfl_xor_sync(0xFFFFFFFFu, p0, o);
        p1 += __shfl_xor_sync(0xFFFFFFFFu, p1, o);
        p2 += __shfl_xor_sync(0xFFFFFFFFu, p2, o);
        p3 += __shfl_xor_sync(0xFFFFFFFFu, p3, o);
    }
    if (l == 0) {
        ((float4*)g_maps)[e] =
            make_float4(p0 + b_map2[0], p1 + b_map2[1], p2 + b_map2[2], p3 + b_map2[3]);
    }
}

// ---------------- per-node: diag = segsum(F^T F), Dinv, diag_n ----------------
__global__ void node_diag_k() {
    int n = blockIdx.x * blockDim.x + threadIdx.x;
    if (n >= NN) return;
    float f00 = 0.f, f01 = 0.f, f11 = 0.f;
    int beg = g_rowptr[n], end = g_rowptr[n + 1];
    const float4* maps4 = (const float4*)g_maps;
    for (int i = beg; i < end; i++) {
        float4 m = maps4[g_adj[i]];
        f00 += m.x * m.x + m.z * m.z;
        f01 += m.x * m.y + m.z * m.w;
        f11 += m.y * m.y + m.w * m.w;
    }
    // analytic D^{-1/2} of symmetric 2x2 (spectral function: basis independent)
    float t = 0.5f * (f00 + f11);
    float dd = 0.5f * (f00 - f11);
    float rad = sqrtf(dd * dd + f01 * f01);
    float l1 = t - rad, l2 = t + rad;
    float s1 = rsqrtf(fmaxf(l1, EPSV));
    float s2 = rsqrtf(fmaxf(l2, EPSV));
    float c0 = 0.5f * (s1 + s2);
    float c1 = (rad > 1e-20f) ? (s2 - s1) / (2.f * rad) : 0.f;
    float D00 = c0 + c1 * dd;
    float D01 = c1 * f01;
    float D11 = c0 - c1 * dd;
    // diag_n = D M D
    float g00 = f00 * D00 + f01 * D01, g01 = f00 * D01 + f01 * D11;
    float g10 = f01 * D00 + f11 * D01, g11 = f01 * D01 + f11 * D11;
    float dn00 = D00 * g00 + D01 * g10, dn01 = D00 * g01 + D01 * g11;
    float dn10 = D01 * g00 + D11 * g10, dn11 = D01 * g01 + D11 * g11;
    ((float4*)g_Dinv)[n] = make_float4(D00, D01, D01, D11);
    ((float4*)g_diagn)[n] = make_float4(dn00, dn01, dn10, dn11);
}

// ---------------- per-edge normalized off-diagonal blocks ----------------
__global__ void edge_offn_k(const int* __restrict__ src, const int* __restrict__ dst) {
    int e = blockIdx.x * blockDim.x + threadIdx.x;
    if (e >= EE) return;
    int r = (e < EH) ? e + EH : e - EH;
    const float4* maps4 = (const float4*)g_maps;
    float4 me = maps4[e];
    float4 mr = maps4[r];
    // off = -(me^T @ mr)
    float o00 = -(me.x * mr.x + me.z * mr.z);
    float o01 = -(me.x * mr.y + me.z * mr.w);
    float o10 = -(me.y * mr.x + me.w * mr.z);
    float o11 = -(me.y * mr.y + me.w * mr.w);
    float4 Ds = ((const float4*)g_Dinv)[src[e]];
    float4 Dd = ((const float4*)g_Dinv)[dst[e]];
    // t = Ds @ off
    float t00 = Ds.x * o00 + Ds.y * o10, t01 = Ds.x * o01 + Ds.y * o11;
    float t10 = Ds.z * o00 + Ds.w * o10, t11 = Ds.z * o01 + Ds.w * o11;
    // off_n = t @ Dd
    float n00 = t00 * Dd.x + t01 * Dd.z, n01 = t00 * Dd.y + t01 * Dd.w;
    float n10 = t10 * Dd.x + t11 * Dd.z, n11 = t10 * Dd.y + t11 * Dd.w;
    ((float4*)g_offn)[e] = make_float4(n00, n01, n10, n11);
}

// ---------------- Ht = W1^T applied to xw2 blocks ----------------
__global__ void ht_k(const float* __restrict__ W1) {
    int i = blockIdx.x * blockDim.x + threadIdx.x;
    if (i >= NN * 64) return;
    int n = i >> 6, g = i & 63;
    float w00 = W1[0], w01 = W1[1], w10 = W1[2], w11 = W1[3];
    float x0 = g_xw2[n * 128 + g];
    float x1 = g_xw2[n * 128 + 64 + g];
    g_Ht[n * 128 + g] = w00 * x0 + w10 * x1;        // Ht[0][g] = W1[0][0]*x0 + W1[1][0]*x1
    g_Ht[n * 128 + 64 + g] = w01 * x0 + w11 * x1;   // Ht[1][g]
}

// ---------------- gather-based sheaf aggregation + elu update (warp per node) -------------
__global__ void __launch_bounds__(256) aggregate_k(const int* __restrict__ dst) {
    int w = threadIdx.x >> 5, l = threadIdx.x & 31;
    int n = blockIdx.x * 8 + w;
    if (n >= NN) return;
    const float* Hn = g_Ht + (size_t)n * 128;
    float ht0a = Hn[l], ht0b = Hn[32 + l], ht1a = Hn[64 + l], ht1b = Hn[96 + l];
    float4 dn = ((const float4*)g_diagn)[n];
    float a0a = dn.x * ht0a + dn.y * ht1a;
    float a0b = dn.x * ht0b + dn.y * ht1b;
    float a1a = dn.z * ht0a + dn.w * ht1a;
    float a1b = dn.z * ht0b + dn.w * ht1b;
    int beg = g_rowptr[n], end = g_rowptr[n + 1];
    const float4* offn4 = (const float4*)g_offn;
    for (int i = beg; i < end; i++) {
        int e = g_adj[i];
        int dd = dst[e];
        float4 o = offn4[e];
        const float* H = g_Ht + (size_t)dd * 128;
        float x0a = H[l], x0b = H[32 + l], x1a = H[64 + l], x1b = H[96 + l];
        a0a += o.x * x0a + o.y * x1a;
        a0b += o.x * x0b + o.y * x1b;
        a1a += o.z * x0a + o.w * x1a;
        a1b += o.z * x0b + o.w * x1b;
    }
    float* h3 = g_h + (size_t)n * 128;
    h3[l] -= eluf(a0a);
    h3[32 + l] -= eluf(a0b);
    h3[64 + l] -= eluf(a1a);
    h3[96 + l] -= eluf(a1b);
}

// ---------------- host ----------------
extern "C" void kernel_launch(void* const* d_in, const int* in_sizes, int n_in,
                              void* d_out, int out_size) {
    (void)in_sizes; (void)n_in; (void)out_size;
    const float* x = (const float*)d_in[0];
    const int* ei = (const int*)d_in[1];
    const int* src = ei;
    const int* dst = ei + EE;
    const float* w_in1 = (const float*)d_in[2];
    const float* b_in1 = (const float*)d_in[3];
    const float* w_in2 = (const float*)d_in[4];
    const float* b_in2 = (const float*)d_in[5];
    const float* w_map1 = (const float*)d_in[6];
    const float* b_map1 = (const float*)d_in[7];
    const float* w_map2 = (const float*)d_in[8];
    const float* b_map2 = (const float*)d_in[9];
    const float* w_out1 = (const float*)d_in[10];
    const float* b_out1 = (const float*)d_in[11];
    const float* w_out2 = (const float*)d_in[12];
    const float* b_out2 = (const float*)d_in[13];
    const float* W1_0 = (const float*)d_in[14];
    const float* W2_0 = (const float*)d_in[15];
    const float* W1_1 = (const float*)d_in[16];
    const float* W2_1 = (const float*)d_in[17];
    float* out = (float*)d_out;

    void *p_h1, *p_h, *p_P, *p_Wab, *p_xw2;
    cudaGetSymbolAddress(&p_h1, g_h1);
    cudaGetSymbolAddress(&p_h, g_h);
    cudaGetSymbolAddress(&p_P, g_P);
    cudaGetSymbolAddress(&p_Wab, g_Wab);
    cudaGetSymbolAddress(&p_xw2, g_xw2);

    // prep: pack Wab + zero counters
    prep_k<<<79, 256>>>(w_map1);

    // input MLP: h1 = relu(x @ w_in1^T + b), h = h1 @ w_in2^T + b
    gemm_tn<true><<<dim3(1, 313), 256>>>(x, w_in1, b_in1, (float*)p_h1, NN, 64, 512);
    gemm_tn<false><<<dim3(2, 313), 256>>>((const float*)p_h1, w_in2, b_in2, (float*)p_h,
                                          NN, 128, 64);
    // per-node A|B partials for the edge MLP
    gemm_tn<false><<<dim3(2, 313), 256>>>((const float*)p_h, (const float*)p_Wab, nullptr,
                                          (float*)p_P, NN, 128, 128);

    // CSR by src
    hist_k<<<1250, 256>>>(src);
    scan_k<<<1, 1024>>>();
    scatter_k<<<1250, 256>>>(src);

    // edge maps, diag blocks, off blocks
    edge_maps_k<<<EE / 8, 256>>>(src, dst, b_map1, w_map2, b_map2);
    node_diag_k<<<79, 256>>>();
    edge_offn_k<<<1250, 256>>>(src, dst);

    // two sheaf-diffusion layers (h3 lives in g_h, updated in place)
    const float* W1s[2] = {W1_0, W1_1};
    const float* W2s[2] = {W2_0, W2_1};
    for (int layer = 0; layer < 2; layer++) {
        gemm_tn<false><<<dim3(1, 625), 256>>>((const float*)p_h, W2s[layer], nullptr,
                                              (float*)p_xw2, 2 * NN, 64, 64);
        ht_k<<<5000, 256>>>(W1s[layer]);
        aggregate_k<<<2500, 256>>>(dst);
    }

    // output MLP
    gemm_tn<true><<<dim3(1, 313), 256>>>((const float*)p_h, w_out1, b_out1, (float*)p_h1,
                                         NN, 64, 128);
    gemm_tn<false><<<dim3(1, 313), 256>>>((const float*)p_h1, w_out2, b_out2, out,
                                          NN, 40, 64);
}